// round 5
// baseline (speedup 1.0000x reference)
#include <cuda_runtime.h>
#include <cuda_fp16.h>

#define BSZ 32
#define TT 512
#define DD 128
#define MM 50
#define NUMC 4096
#define AWC (NUMC + DD)
#define G4 512
#define RR (BSZ * TT)

// ---------------- scratch (static device arrays; no allocation) ----------------
__device__ float g_k[RR * DD];
__device__ float g_yq[RR * DD];
__device__ float g_w[RR * MM];
__device__ unsigned long long g_pack[RR * 2];
__device__ int g_prev[RR];
__device__ int g_match[RR];
__device__ float g_f[RR * DD];
__device__ float g_gi[RR * G4];
__device__ float g_H[RR * DD];
__device__ float g_C[RR * DD];

__device__ __forceinline__ float warp_sum(float v) {
#pragma unroll
    for (int o = 16; o; o >>= 1) v += __shfl_xor_sync(0xffffffffu, v, o);
    return v;
}

__device__ __forceinline__ half2 as_h2(unsigned u) { return *reinterpret_cast<half2*>(&u); }
__device__ __forceinline__ float sigf(float x) { return 1.f / (1.f + __expf(-x)); }
__device__ __forceinline__ float h2sumf(half2 v) {
    const float2 e = __half22float2(v);
    return e.x + e.y;
}
__device__ __forceinline__ float quad_sum(float v) {
    v += __shfl_xor_sync(0xffffffffu, v, 1);
    v += __shfl_xor_sync(0xffffffffu, v, 2);
    return v;
}

// ---------------- Kernel A: gather + logits + softmax + quantize/pack ----------
__global__ __launch_bounds__(256) void kA(const int* __restrict__ q,
                                          const int* __restrict__ r,
                                          const float* __restrict__ k_emb,
                                          const float* __restrict__ Mk,
                                          const float* __restrict__ aW) {
    __shared__ float sMk[MM * DD];
    __shared__ float sk[DD];
    __shared__ float slog[MM];
    const int tid = threadIdx.x;
    for (int i = tid; i < MM * DD; i += 256) sMk[i] = Mk[i];
    const int base = blockIdx.x * 64;
    const int warp = tid >> 5, lane = tid & 31;

    for (int p = 0; p < 64; p++) {
        const int idx = base + p;
        __syncthreads();
        if (tid < DD) {
            const int qv = q[idx];
            const float kv = k_emb[qv * DD + tid];
            sk[tid] = kv;
            g_k[idx * DD + tid] = kv;
            g_yq[idx * DD + tid] = aW[tid * AWC + qv] * (float)r[idx];
        }
        __syncthreads();
        for (int m = warp; m < MM; m += 8) {
            float s = 0.f;
#pragma unroll
            for (int c = 0; c < 4; c++) s = fmaf(sk[c * 32 + lane], sMk[m * DD + c * 32 + lane], s);
            s = warp_sum(s);
            if (lane == 0) slog[m] = s;
        }
        __syncthreads();
        if (warp == 0) {
            float l0 = (lane < MM) ? slog[lane] : -1e30f;
            float l1 = (lane + 32 < MM) ? slog[lane + 32] : -1e30f;
            float mx = fmaxf(l0, l1);
#pragma unroll
            for (int o = 16; o; o >>= 1) mx = fmaxf(mx, __shfl_xor_sync(0xffffffffu, mx, o));
            float e0 = (lane < MM) ? expf(l0 - mx) : 0.f;
            float e1 = (lane + 32 < MM) ? expf(l1 - mx) : 0.f;
            float ssum = warp_sum(e0 + e1);
            float w0 = e0 / ssum, w1 = e1 / ssum;
            if (lane < MM) g_w[idx * MM + lane] = w0;
            if (lane + 32 < MM) g_w[idx * MM + lane + 32] = w1;
            const float ta = 0.075f;
            const float dba = (float)(0.088 - 0.075);
            const float dcb = (float)(1.0 - 0.088);
            float tw0 = fmaxf(fminf((w0 - ta) / dba, (1.0f - w0) / dcb), 0.f);
            float tw1 = fmaxf(fminf((w1 - ta) / dba, (1.0f - w1) / dcb), 0.f);
            int c0 = (lane < MM) ? (tw0 >= 0.6f ? 2 : (tw0 >= 0.1f ? 1 : 0)) : 0;
            int c1 = (lane + 32 < MM) ? (tw1 >= 0.6f ? 2 : (tw1 >= 0.1f ? 1 : 0)) : 0;
            unsigned b00 = __ballot_sync(0xffffffffu, c0 & 1);
            unsigned b01 = __ballot_sync(0xffffffffu, c0 >> 1);
            unsigned b10 = __ballot_sync(0xffffffffu, c1 & 1);
            unsigned b11 = __ballot_sync(0xffffffffu, c1 >> 1);
            if (lane == 0) {
                g_pack[idx * 2 + 0] = (unsigned long long)b00 | ((unsigned long long)b01 << 32);
                g_pack[idx * 2 + 1] = (unsigned long long)b10 | ((unsigned long long)b11 << 32);
            }
        }
    }
}

// ---------------- Kernel B: matched/prev via warp ballot backward scan ---------
__global__ __launch_bounds__(256) void kB() {
    const int gw = blockIdx.x * 8 + (threadIdx.x >> 5);
    const int lane = threadIdx.x & 31;
    const int b = gw / TT, i = gw % TT;
    const unsigned long long m0 = g_pack[gw * 2], m1 = g_pack[gw * 2 + 1];
    const unsigned long long* rp = &g_pack[(size_t)b * TT * 2];
    int prev = 0, matched = 0;
    for (int base = i - 1; base >= 0; base -= 32) {
        const int j = base - lane;
        const bool eq = (j >= 0) && (rp[j * 2] == m0) && (rp[j * 2 + 1] == m1);
        const unsigned msk = __ballot_sync(0xffffffffu, eq);
        if (msk) { matched = 1; prev = base - (__ffs(msk) - 1); break; }
    }
    if (lane == 0) { g_prev[gw] = prev; g_match[gw] = matched; }
}

// ---------------- Kernel C: memory-network scan, 512 threads, split-K=4 --------
// smem: eS 0..32768 | adS ..65536 | xh4 ..66560 | fh4 ..67072 | yh4 ..67584 | wbuf ..68608
#define C_SMEM 68608
__global__ __launch_bounds__(512) void kC(const float* __restrict__ fW,
                                          const float* __restrict__ fb,
                                          const float* __restrict__ aW,
                                          const float* __restrict__ ab,
                                          const float* __restrict__ eW,
                                          const float* __restrict__ eb,
                                          const float* __restrict__ addW,
                                          const float* __restrict__ addb,
                                          const float* __restrict__ Mv0) {
    extern __shared__ char sm[];
    uint4* eS = (uint4*)sm;                // [16][128] uint4
    uint4* adS = (uint4*)(sm + 32768);     // [16][128]
    uint4* xh4 = (uint4*)(sm + 65536);     // [2][32]
    uint4* fh4 = (uint4*)(sm + 66560);     // [2][16]
    uint4* yh4 = (uint4*)(sm + 67072);     // [2][16]
    float* wbuf = (float*)(sm + 67584);    // [2 par][2 batch][64]
    half2* xh2 = (half2*)xh4;
    half2* fh2 = (half2*)fh4;
    half2* yh2 = (half2*)yh4;

    const int tid = threadIdx.x;
    const int o = tid >> 2, p = tid & 3;
    const int b0 = blockIdx.x * 2;
    const half2 z = __float2half2_rn(0.f);

    // e/a weights into smem (half2x4 rows)
    for (int i = tid; i < 64 * 128; i += 512) {
        const int jp = i >> 7, oo = i & 127;
        const int d = (((jp >> 2) * 128 + oo) << 2) + (jp & 3);
        ((half2*)eS)[d] = __floats2half2_rn(eW[oo * 128 + 2 * jp], eW[oo * 128 + 2 * jp + 1]);
        ((half2*)adS)[d] = __floats2half2_rn(addW[oo * 128 + 2 * jp], addW[oo * 128 + 2 * jp + 1]);
    }
    // f/y weights into registers (thread owns output o, input slice p)
    half2 wf[32];
    {
        const float4* src = (const float4*)(fW + o * 256 + p * 64);
#pragma unroll
        for (int j = 0; j < 16; j++) {
            const float4 v = src[j];
            wf[2 * j] = __floats2half2_rn(v.x, v.y);
            wf[2 * j + 1] = __floats2half2_rn(v.z, v.w);
        }
    }
    half2 wy[16];
    {
        const float4* src = (const float4*)(aW + o * AWC + NUMC + p * 32);
#pragma unroll
        for (int j = 0; j < 8; j++) {
            const float4 v = src[j];
            wy[2 * j] = __floats2half2_rn(v.x, v.y);
            wy[2 * j + 1] = __floats2half2_rn(v.z, v.w);
        }
    }
    float Mva[13], Mvb[13];
#pragma unroll
    for (int i = 0; i < 13; i++) {
        const int m = p + 4 * i;
        const float v = (m < MM) ? Mv0[m * DD + o] : 0.f;
        Mva[i] = v; Mvb[i] = v;
    }
    const float bfv = fb[o], bav = ab[o], bev = eb[o], badv = addb[o];
    __syncthreads();

    for (int t = 0; t < TT; t++) {
        const int idx0 = b0 * TT + t, idx1 = idx0 + TT;
        const int par = (t & 1) << 7;
        // phase 0: stage w and k
        if (tid < MM) {
            wbuf[par + tid] = g_w[idx0 * MM + tid];
            wbuf[par + 64 + tid] = g_w[idx1 * MM + tid];
        }
        if (tid < 128) {
            const float k0 = g_k[idx0 * DD + tid], k1 = g_k[idx1 * DD + tid];
            const float o0 = __shfl_xor_sync(0xffffffffu, k0, 1);
            const float o1 = __shfl_xor_sync(0xffffffffu, k1, 1);
            if (!(tid & 1)) {
                xh2[64 + (tid >> 1)] = __floats2half2_rn(k0, o0);
                xh2[128 + 64 + (tid >> 1)] = __floats2half2_rn(k1, o1);
            }
        }
        const float yq0 = g_yq[idx0 * DD + o], yq1 = g_yq[idx1 * DD + o];
        __syncthreads();  // B1

        // phase 1: read = w @ Mv (split over m mod 4)
        float ra = 0.f, rb = 0.f;
#pragma unroll
        for (int i = 0; i < 13; i++) {
            const int m = p + 4 * i;
            if (m < MM) {
                ra = fmaf(wbuf[par + m], Mva[i], ra);
                rb = fmaf(wbuf[par + 64 + m], Mvb[i], rb);
            }
        }
        ra = quad_sum(ra);
        rb = quad_sum(rb);
        {
            const float qa = __shfl_xor_sync(0xffffffffu, ra, 4);
            const float qb = __shfl_xor_sync(0xffffffffu, rb, 4);
            if (p == 0 && !(o & 1)) {
                xh2[o >> 1] = __floats2half2_rn(ra, qa);
                xh2[128 + (o >> 1)] = __floats2half2_rn(rb, qb);
            }
        }
        __syncthreads();  // B2

        // phase 2: f = tanh([read,k] @ fW.T + fb)
        half2 A0[4] = {z, z, z, z}, A1[4] = {z, z, z, z};
#pragma unroll
        for (int j = 0; j < 8; j++) {
            const uint4 x0 = xh4[p * 8 + j];
            const uint4 x1 = xh4[32 + p * 8 + j];
            A0[0] = __hfma2(wf[4 * j + 0], as_h2(x0.x), A0[0]);
            A0[1] = __hfma2(wf[4 * j + 1], as_h2(x0.y), A0[1]);
            A0[2] = __hfma2(wf[4 * j + 2], as_h2(x0.z), A0[2]);
            A0[3] = __hfma2(wf[4 * j + 3], as_h2(x0.w), A0[3]);
            A1[0] = __hfma2(wf[4 * j + 0], as_h2(x1.x), A1[0]);
            A1[1] = __hfma2(wf[4 * j + 1], as_h2(x1.y), A1[1]);
            A1[2] = __hfma2(wf[4 * j + 2], as_h2(x1.z), A1[2]);
            A1[3] = __hfma2(wf[4 * j + 3], as_h2(x1.w), A1[3]);
        }
        float s0 = (h2sumf(A0[0]) + h2sumf(A0[1])) + (h2sumf(A0[2]) + h2sumf(A0[3]));
        float s1 = (h2sumf(A1[0]) + h2sumf(A1[1])) + (h2sumf(A1[2]) + h2sumf(A1[3]));
        s0 = quad_sum(s0);
        s1 = quad_sum(s1);
        const float fv0 = tanhf(s0 + bfv);
        const float fv1 = tanhf(s1 + bfv);
        if (p == 0) {
            g_f[idx0 * DD + o] = fv0;
            g_f[idx1 * DD + o] = fv1;
        }
        {
            const float q0 = __shfl_xor_sync(0xffffffffu, fv0, 4);
            const float q1 = __shfl_xor_sync(0xffffffffu, fv1, 4);
            if (p == 0 && !(o & 1)) {
                fh2[o >> 1] = __floats2half2_rn(fv0, q0);
                fh2[64 + (o >> 1)] = __floats2half2_rn(fv1, q1);
            }
        }
        __syncthreads();  // B3

        // phase 3: y = yq + f @ aWf.T + ab
        half2 Y0[2] = {z, z}, Y1[2] = {z, z};
#pragma unroll
        for (int j = 0; j < 4; j++) {
            const uint4 x0 = fh4[p * 4 + j];
            const uint4 x1 = fh4[16 + p * 4 + j];
            Y0[0] = __hfma2(wy[4 * j + 0], as_h2(x0.x), Y0[0]);
            Y0[1] = __hfma2(wy[4 * j + 1], as_h2(x0.y), Y0[1]);
            Y0[0] = __hfma2(wy[4 * j + 2], as_h2(x0.z), Y0[0]);
            Y0[1] = __hfma2(wy[4 * j + 3], as_h2(x0.w), Y0[1]);
            Y1[0] = __hfma2(wy[4 * j + 0], as_h2(x1.x), Y1[0]);
            Y1[1] = __hfma2(wy[4 * j + 1], as_h2(x1.y), Y1[1]);
            Y1[0] = __hfma2(wy[4 * j + 2], as_h2(x1.z), Y1[0]);
            Y1[1] = __hfma2(wy[4 * j + 3], as_h2(x1.w), Y1[1]);
        }
        float t0 = h2sumf(Y0[0]) + h2sumf(Y0[1]);
        float t1 = h2sumf(Y1[0]) + h2sumf(Y1[1]);
        t0 = quad_sum(t0);
        t1 = quad_sum(t1);
        const float y0 = t0 + bav + yq0;
        const float y1 = t1 + bav + yq1;
        {
            const float q0 = __shfl_xor_sync(0xffffffffu, y0, 4);
            const float q1 = __shfl_xor_sync(0xffffffffu, y1, 4);
            if (p == 0 && !(o & 1)) {
                yh2[o >> 1] = __floats2half2_rn(y0, q0);
                yh2[64 + (o >> 1)] = __floats2half2_rn(y1, q1);
            }
        }
        __syncthreads();  // B4

        // phase 4: e = sigmoid(y@eW.T+eb), a = tanh(y@addW.T+addb)
        half2 E0[2] = {z, z}, E1[2] = {z, z}, D0[2] = {z, z}, D1[2] = {z, z};
#pragma unroll
        for (int j = 0; j < 4; j++) {
            const uint4 we = eS[(p * 4 + j) * 128 + o];
            const uint4 wa = adS[(p * 4 + j) * 128 + o];
            const uint4 x0 = yh4[p * 4 + j];
            const uint4 x1 = yh4[16 + p * 4 + j];
            E0[0] = __hfma2(as_h2(we.x), as_h2(x0.x), E0[0]);
            E0[1] = __hfma2(as_h2(we.y), as_h2(x0.y), E0[1]);
            E0[0] = __hfma2(as_h2(we.z), as_h2(x0.z), E0[0]);
            E0[1] = __hfma2(as_h2(we.w), as_h2(x0.w), E0[1]);
            D0[0] = __hfma2(as_h2(wa.x), as_h2(x0.x), D0[0]);
            D0[1] = __hfma2(as_h2(wa.y), as_h2(x0.y), D0[1]);
            D0[0] = __hfma2(as_h2(wa.z), as_h2(x0.z), D0[0]);
            D0[1] = __hfma2(as_h2(wa.w), as_h2(x0.w), D0[1]);
            E1[0] = __hfma2(as_h2(we.x), as_h2(x1.x), E1[0]);
            E1[1] = __hfma2(as_h2(we.y), as_h2(x1.y), E1[1]);
            E1[0] = __hfma2(as_h2(we.z), as_h2(x1.z), E1[0]);
            E1[1] = __hfma2(as_h2(we.w), as_h2(x1.w), E1[1]);
            D1[0] = __hfma2(as_h2(wa.x), as_h2(x1.x), D1[0]);
            D1[1] = __hfma2(as_h2(wa.y), as_h2(x1.y), D1[1]);
            D1[0] = __hfma2(as_h2(wa.z), as_h2(x1.z), D1[0]);
            D1[1] = __hfma2(as_h2(wa.w), as_h2(x1.w), D1[1]);
        }
        float se0 = quad_sum(h2sumf(E0[0]) + h2sumf(E0[1]));
        float se1 = quad_sum(h2sumf(E1[0]) + h2sumf(E1[1]));
        float sd0 = quad_sum(h2sumf(D0[0]) + h2sumf(D0[1]));
        float sd1 = quad_sum(h2sumf(D1[0]) + h2sumf(D1[1]));
        const float ev0 = sigf(se0 + bev), av0 = tanhf(sd0 + badv);
        const float ev1 = sigf(se1 + bev), av1 = tanhf(sd1 + badv);

        // phase 5: Mv update (register slice)
#pragma unroll
        for (int i = 0; i < 13; i++) {
            const int m = p + 4 * i;
            if (m < MM) {
                const float wm0 = wbuf[par + m];
                const float wm1 = wbuf[par + 64 + m];
                Mva[i] = fmaf(wm0, fmaf(-ev0, Mva[i], av0), Mva[i]);
                Mvb[i] = fmaf(wm1, fmaf(-ev1, Mvb[i], av1), Mvb[i]);
            }
        }
    }
}

// ---------------- Kernel D: gi = f_all @ Wih.T + (bih + bhh) -------------------
__global__ __launch_bounds__(256) void kD(const float* __restrict__ Wih,
                                          const float* __restrict__ bih,
                                          const float* __restrict__ bhh) {
    __shared__ float sA[64][68];
    __shared__ float sB[64][68];
    const int tid = threadIdx.x;
    const int row0 = blockIdx.x * 64;
    const int n0 = blockIdx.y * 64;
    const int tx = tid & 15, ty = tid >> 4;
    float acc[4][4];
#pragma unroll
    for (int i = 0; i < 4; i++)
#pragma unroll
        for (int j = 0; j < 4; j++) acc[i][j] = 0.f;

    for (int kk = 0; kk < 128; kk += 64) {
        __syncthreads();
#pragma unroll
        for (int l = 0; l < 4; l++) {
            const int li = tid + l * 256;
            const int m = li >> 4;
            const int kq = li & 15;
            float4 v = *(const float4*)&g_f[(size_t)(row0 + m) * DD + kk + kq * 4];
            sA[kq * 4 + 0][m] = v.x; sA[kq * 4 + 1][m] = v.y;
            sA[kq * 4 + 2][m] = v.z; sA[kq * 4 + 3][m] = v.w;
            float4 u = *(const float4*)&Wih[(size_t)(n0 + m) * DD + kk + kq * 4];
            sB[kq * 4 + 0][m] = u.x; sB[kq * 4 + 1][m] = u.y;
            sB[kq * 4 + 2][m] = u.z; sB[kq * 4 + 3][m] = u.w;
        }
        __syncthreads();
#pragma unroll 8
        for (int k = 0; k < 64; k++) {
            float4 a4 = *(const float4*)&sA[k][ty * 4];
            float4 b4 = *(const float4*)&sB[k][tx * 4];
            acc[0][0] += a4.x * b4.x; acc[0][1] += a4.x * b4.y;
            acc[0][2] += a4.x * b4.z; acc[0][3] += a4.x * b4.w;
            acc[1][0] += a4.y * b4.x; acc[1][1] += a4.y * b4.y;
            acc[1][2] += a4.y * b4.z; acc[1][3] += a4.y * b4.w;
            acc[2][0] += a4.z * b4.x; acc[2][1] += a4.z * b4.y;
            acc[2][2] += a4.z * b4.z; acc[2][3] += a4.z * b4.w;
            acc[3][0] += a4.w * b4.x; acc[3][1] += a4.w * b4.y;
            acc[3][2] += a4.w * b4.z; acc[3][3] += a4.w * b4.w;
        }
    }
#pragma unroll
    for (int i = 0; i < 4; i++) {
        const int rrow = row0 + ty * 4 + i;
#pragma unroll
        for (int j = 0; j < 4; j++) {
            const int n = n0 + tx * 4 + j;
            g_gi[(size_t)rrow * G4 + n] = acc[i][j] + bih[n] + bhh[n];
        }
    }
}

// ---------------- Kernel E: LSTM scan, 512 threads, Whh in registers -----------
__global__ __launch_bounds__(512) void kE(const float* __restrict__ Whh,
                                          const float* __restrict__ pW,
                                          const float* __restrict__ pb,
                                          float* __restrict__ out) {
    __shared__ uint4 hh4[32];      // [2 batches][16]
    __shared__ float sgate[2][G4];
    __shared__ float red[8];
    half2* hh2 = (half2*)hh4;
    const int tid = threadIdx.x;
    const int b0 = blockIdx.x * 2;
    const half2 z = __float2half2_rn(0.f);

    // thread owns gate-output row tid of Whh, in registers
    half2 whh[64];
    {
        const float4* src = (const float4*)(Whh + (size_t)tid * DD);
#pragma unroll
        for (int j = 0; j < 32; j++) {
            const float4 v = src[j];
            whh[2 * j] = __floats2half2_rn(v.x, v.y);
            whh[2 * j + 1] = __floats2half2_rn(v.z, v.w);
        }
    }
    const float pw = (tid < 256) ? pW[tid & 127] : 0.f;
    const float pbv = pb[0];
    float h = 0.f, c = 0.f;  // state for tid<256: batch=tid>>7, d=tid&127
    __syncthreads();

    for (int t = 0; t < TT; t++) {
        const int idx0 = b0 * TT + t, idx1 = idx0 + TT;
        float cin = 0.f;
        if (tid < 256) {
            const int bb = tid >> 7, d = tid & 127;
            const int idx = bb ? idx1 : idx0;
            const int bB = b0 + bb;
            float hv;
            if (g_match[idx]) {
                const int pv = g_prev[idx];
                hv = g_H[(size_t)(bB * TT + pv) * DD + d];
                cin = g_C[(size_t)(bB * TT + pv) * DD + d];
            } else {
                hv = h; cin = c;
            }
            const float o_ = __shfl_xor_sync(0xffffffffu, hv, 1);
            if (!(tid & 1)) hh2[bb * 64 + (d >> 1)] = __floats2half2_rn(hv, o_);
        }
        const float gi0v = g_gi[(size_t)idx0 * G4 + tid];
        const float gi1v = g_gi[(size_t)idx1 * G4 + tid];
        __syncthreads();  // B1

        half2 a0[4] = {z, z, z, z}, a1[4] = {z, z, z, z};
#pragma unroll
        for (int j = 0; j < 16; j++) {
            const uint4 x0 = hh4[j];
            const uint4 x1 = hh4[16 + j];
            a0[0] = __hfma2(whh[4 * j + 0], as_h2(x0.x), a0[0]);
            a0[1] = __hfma2(whh[4 * j + 1], as_h2(x0.y), a0[1]);
            a0[2] = __hfma2(whh[4 * j + 2], as_h2(x0.z), a0[2]);
            a0[3] = __hfma2(whh[4 * j + 3], as_h2(x0.w), a0[3]);
            a1[0] = __hfma2(whh[4 * j + 0], as_h2(x1.x), a1[0]);
            a1[1] = __hfma2(whh[4 * j + 1], as_h2(x1.y), a1[1]);
            a1[2] = __hfma2(whh[4 * j + 2], as_h2(x1.z), a1[2]);
            a1[3] = __hfma2(whh[4 * j + 3], as_h2(x1.w), a1[3]);
        }
        sgate[0][tid] = gi0v + (h2sumf(a0[0]) + h2sumf(a0[1])) + (h2sumf(a0[2]) + h2sumf(a0[3]));
        sgate[1][tid] = gi1v + (h2sumf(a1[0]) + h2sumf(a1[1])) + (h2sumf(a1[2]) + h2sumf(a1[3]));
        __syncthreads();  // B2

        if (tid < 256) {
            const int bb = tid >> 7, d = tid & 127;
            const float gI = sgate[bb][d];
            const float gF = sgate[bb][128 + d];
            const float gG = sgate[bb][256 + d];
            const float gO = sgate[bb][384 + d];
            c = sigf(gF) * cin + sigf(gI) * tanhf(gG);
            h = sigf(gO) * tanhf(c);
            const int idx = bb ? idx1 : idx0;
            g_H[(size_t)idx * DD + d] = h;
            g_C[(size_t)idx * DD + d] = c;
            const float pv_ = warp_sum(h * pw);
            if (!(tid & 31)) red[tid >> 5] = pv_;
        }
        __syncthreads();  // B3
        if (tid == 0) {
            out[idx0] = sigf(red[0] + red[1] + red[2] + red[3] + pbv);
            out[idx1] = sigf(red[4] + red[5] + red[6] + red[7] + pbv);
        }
    }
}

// ---------------- launch ----------------
extern "C" void kernel_launch(void* const* d_in, const int* in_sizes, int n_in,
                              void* d_out, int out_size) {
    const int* q = (const int*)d_in[0];
    const int* r = (const int*)d_in[1];
    const float* k_emb = (const float*)d_in[2];
    const float* Mk = (const float*)d_in[3];
    const float* Mv0 = (const float*)d_in[4];
    const float* fW = (const float*)d_in[5];
    const float* fb = (const float*)d_in[6];
    const float* aW = (const float*)d_in[7];
    const float* ab = (const float*)d_in[8];
    const float* eW = (const float*)d_in[9];
    const float* eb = (const float*)d_in[10];
    const float* addW = (const float*)d_in[11];
    const float* addb = (const float*)d_in[12];
    const float* Wih = (const float*)d_in[13];
    const float* Whh = (const float*)d_in[14];
    const float* bih = (const float*)d_in[15];
    const float* bhh = (const float*)d_in[16];
    const float* pW = (const float*)d_in[17];
    const float* pb = (const float*)d_in[18];
    float* out = (float*)d_out;

    cudaFuncSetAttribute(kC, cudaFuncAttributeMaxDynamicSharedMemorySize, C_SMEM);

    kA<<<256, 256>>>(q, r, k_emb, Mk, aW);
    kB<<<RR / 8, 256>>>();
    kC<<<BSZ / 2, 512, C_SMEM>>>(fW, fb, aW, ab, eW, eb, addW, addb, Mv0);
    kD<<<dim3(RR / 64, G4 / 64), 256>>>(Wih, bih, bhh);
    kE<<<BSZ / 2, 512>>>(Whh, pW, pb, out);
}

// round 6
// speedup vs baseline: 1.1279x; 1.1279x over previous
#include <cuda_runtime.h>
#include <cuda_fp16.h>

#define BSZ 32
#define TT 512
#define DD 128
#define MM 50
#define NUMC 4096
#define AWC (NUMC + DD)
#define G4 512
#define RR (BSZ * TT)

// ---------------- scratch (static device arrays; no allocation) ----------------
__device__ float g_k[RR * DD];
__device__ float g_yq[RR * DD];
__device__ float g_w[RR * MM];
__device__ unsigned long long g_pack[RR * 2];
__device__ int g_prev[RR];
__device__ int g_match[RR];
__device__ float g_f[RR * DD];
__device__ float g_gi[RR * G4];
__device__ float g_H[RR * DD];
__device__ float g_C[RR * DD];

__device__ __forceinline__ float warp_sum(float v) {
#pragma unroll
    for (int o = 16; o; o >>= 1) v += __shfl_xor_sync(0xffffffffu, v, o);
    return v;
}

__device__ __forceinline__ half2 as_h2(unsigned u) { return *reinterpret_cast<half2*>(&u); }
__device__ __forceinline__ float sigf(float x) { return 1.f / (1.f + __expf(-x)); }
__device__ __forceinline__ float h2sumf(half2 v) {
    const float2 e = __half22float2(v);
    return e.x + e.y;
}

// ---------------- Kernel A: gather + logits + softmax + quantize/pack ----------
__global__ __launch_bounds__(256) void kA(const int* __restrict__ q,
                                          const int* __restrict__ r,
                                          const float* __restrict__ k_emb,
                                          const float* __restrict__ Mk,
                                          const float* __restrict__ aW) {
    __shared__ float sMk[MM * DD];
    __shared__ float sk[DD];
    __shared__ float slog[MM];
    const int tid = threadIdx.x;
    for (int i = tid; i < MM * DD; i += 256) sMk[i] = Mk[i];
    const int base = blockIdx.x * 64;
    const int warp = tid >> 5, lane = tid & 31;

    for (int p = 0; p < 64; p++) {
        const int idx = base + p;
        __syncthreads();
        if (tid < DD) {
            const int qv = q[idx];
            const float kv = k_emb[qv * DD + tid];
            sk[tid] = kv;
            g_k[idx * DD + tid] = kv;
            g_yq[idx * DD + tid] = aW[tid * AWC + qv] * (float)r[idx];
        }
        __syncthreads();
        for (int m = warp; m < MM; m += 8) {
            float s = 0.f;
#pragma unroll
            for (int c = 0; c < 4; c++) s = fmaf(sk[c * 32 + lane], sMk[m * DD + c * 32 + lane], s);
            s = warp_sum(s);
            if (lane == 0) slog[m] = s;
        }
        __syncthreads();
        if (warp == 0) {
            float l0 = (lane < MM) ? slog[lane] : -1e30f;
            float l1 = (lane + 32 < MM) ? slog[lane + 32] : -1e30f;
            float mx = fmaxf(l0, l1);
#pragma unroll
            for (int o = 16; o; o >>= 1) mx = fmaxf(mx, __shfl_xor_sync(0xffffffffu, mx, o));
            float e0 = (lane < MM) ? expf(l0 - mx) : 0.f;
            float e1 = (lane + 32 < MM) ? expf(l1 - mx) : 0.f;
            float ssum = warp_sum(e0 + e1);
            float w0 = e0 / ssum, w1 = e1 / ssum;
            if (lane < MM) g_w[idx * MM + lane] = w0;
            if (lane + 32 < MM) g_w[idx * MM + lane + 32] = w1;
            const float ta = 0.075f;
            const float dba = (float)(0.088 - 0.075);
            const float dcb = (float)(1.0 - 0.088);
            float tw0 = fmaxf(fminf((w0 - ta) / dba, (1.0f - w0) / dcb), 0.f);
            float tw1 = fmaxf(fminf((w1 - ta) / dba, (1.0f - w1) / dcb), 0.f);
            int c0 = (lane < MM) ? (tw0 >= 0.6f ? 2 : (tw0 >= 0.1f ? 1 : 0)) : 0;
            int c1 = (lane + 32 < MM) ? (tw1 >= 0.6f ? 2 : (tw1 >= 0.1f ? 1 : 0)) : 0;
            unsigned b00 = __ballot_sync(0xffffffffu, c0 & 1);
            unsigned b01 = __ballot_sync(0xffffffffu, c0 >> 1);
            unsigned b10 = __ballot_sync(0xffffffffu, c1 & 1);
            unsigned b11 = __ballot_sync(0xffffffffu, c1 >> 1);
            if (lane == 0) {
                g_pack[idx * 2 + 0] = (unsigned long long)b00 | ((unsigned long long)b01 << 32);
                g_pack[idx * 2 + 1] = (unsigned long long)b10 | ((unsigned long long)b11 << 32);
            }
        }
    }
}

// ---------------- Kernel B: matched/prev via warp ballot backward scan ---------
__global__ __launch_bounds__(256) void kB() {
    const int gw = blockIdx.x * 8 + (threadIdx.x >> 5);
    const int lane = threadIdx.x & 31;
    const int b = gw / TT, i = gw % TT;
    const unsigned long long m0 = g_pack[gw * 2], m1 = g_pack[gw * 2 + 1];
    const unsigned long long* rp = &g_pack[(size_t)b * TT * 2];
    int prev = 0, matched = 0;
    for (int base = i - 1; base >= 0; base -= 32) {
        const int j = base - lane;
        const bool eq = (j >= 0) && (rp[j * 2] == m0) && (rp[j * 2 + 1] == m1);
        const unsigned msk = __ballot_sync(0xffffffffu, eq);
        if (msk) { matched = 1; prev = base - (__ffs(msk) - 1); break; }
    }
    if (lane == 0) { g_prev[gw] = prev; g_match[gw] = matched; }
}

// ---------------- Kernel C: memory-network scan, 256 thr = 2 groups x 2 batches
// smem: fS 0..65536 | aS ..98304 | eS ..131072 | adS ..163840
//       xh4[2g][64] ..165888 | fh4[2g][32] ..166912 | yh4[2g][32] ..167936
//       wbuf[2g][256f] ..169984
#define C_SMEM 169984
__global__ __launch_bounds__(256) void kC(const float* __restrict__ fW,
                                          const float* __restrict__ fb,
                                          const float* __restrict__ aW,
                                          const float* __restrict__ ab,
                                          const float* __restrict__ eW,
                                          const float* __restrict__ eb,
                                          const float* __restrict__ addW,
                                          const float* __restrict__ addb,
                                          const float* __restrict__ Mv0) {
    extern __shared__ char sm[];
    uint4* fS = (uint4*)sm;
    uint4* aS = (uint4*)(sm + 65536);
    uint4* eS = (uint4*)(sm + 98304);
    uint4* adS = (uint4*)(sm + 131072);

    const int tid = threadIdx.x;
    const int grp = tid >> 7, lt = tid & 127;
    uint4* xh4 = (uint4*)(sm + 163840) + grp * 64;   // [2 batch][32]
    uint4* fh4 = (uint4*)(sm + 165888) + grp * 32;   // [2 batch][16]
    uint4* yh4 = (uint4*)(sm + 166912) + grp * 32;   // [2 batch][16]
    float* wbuf = (float*)(sm + 167936) + grp * 256; // [2 par][2 batch][64]
    half2* xh2 = (half2*)xh4;
    half2* fh2 = (half2*)fh4;
    half2* yh2 = (half2*)yh4;

    const int b0 = blockIdx.x * 4 + grp * 2;

    for (int i = tid; i < 128 * 128; i += 256) {
        const int jp = i >> 7, o = i & 127;
        ((half2*)fS)[(((jp >> 2) * 128 + o) << 2) + (jp & 3)] =
            __floats2half2_rn(fW[o * 256 + 2 * jp], fW[o * 256 + 2 * jp + 1]);
    }
    for (int i = tid; i < 64 * 128; i += 256) {
        const int jp = i >> 7, o = i & 127;
        const int d = (((jp >> 2) * 128 + o) << 2) + (jp & 3);
        ((half2*)aS)[d] =
            __floats2half2_rn(aW[o * AWC + NUMC + 2 * jp], aW[o * AWC + NUMC + 2 * jp + 1]);
        ((half2*)eS)[d] = __floats2half2_rn(eW[o * 128 + 2 * jp], eW[o * 128 + 2 * jp + 1]);
        ((half2*)adS)[d] = __floats2half2_rn(addW[o * 128 + 2 * jp], addW[o * 128 + 2 * jp + 1]);
    }
    const float bfv = fb[lt], bav = ab[lt], bev = eb[lt], badv = addb[lt];
    float Mva[MM], Mvb[MM];
#pragma unroll
    for (int m = 0; m < MM; m++) {
        const float v = Mv0[m * DD + lt];
        Mva[m] = v; Mvb[m] = v;
    }
    __syncthreads();

    const half2 z = __float2half2_rn(0.f);
    for (int t = 0; t < TT; t++) {
        const int idx0 = b0 * TT + t, idx1 = idx0 + TT;
        const int par = (t & 1) << 7;
        if (lt < MM) {
            wbuf[par + lt] = g_w[idx0 * MM + lt];
            wbuf[par + 64 + lt] = g_w[idx1 * MM + lt];
        }
        {
            const float k0 = g_k[idx0 * DD + lt], k1 = g_k[idx1 * DD + lt];
            const float o0 = __shfl_xor_sync(0xffffffffu, k0, 1);
            const float o1 = __shfl_xor_sync(0xffffffffu, k1, 1);
            if (!(lt & 1)) {
                xh2[64 + (lt >> 1)] = __floats2half2_rn(k0, o0);
                xh2[128 + 64 + (lt >> 1)] = __floats2half2_rn(k1, o1);
            }
        }
        const float yq0 = g_yq[idx0 * DD + lt], yq1 = g_yq[idx1 * DD + lt];
        __syncthreads();  // 1

        // read = w @ Mv (registers)
        float ra0 = 0.f, ra1 = 0.f, rb0 = 0.f, rb1 = 0.f;
#pragma unroll
        for (int m = 0; m < MM; m += 2) {
            ra0 = fmaf(wbuf[par + m], Mva[m], ra0);
            ra1 = fmaf(wbuf[par + m + 1], Mva[m + 1], ra1);
            rb0 = fmaf(wbuf[par + 64 + m], Mvb[m], rb0);
            rb1 = fmaf(wbuf[par + 64 + m + 1], Mvb[m + 1], rb1);
        }
        {
            const float rA = ra0 + ra1, rB = rb0 + rb1;
            const float oA = __shfl_xor_sync(0xffffffffu, rA, 1);
            const float oB = __shfl_xor_sync(0xffffffffu, rB, 1);
            if (!(lt & 1)) {
                xh2[lt >> 1] = __floats2half2_rn(rA, oA);
                xh2[128 + (lt >> 1)] = __floats2half2_rn(rB, oB);
            }
        }
        __syncthreads();  // 2

        // f = tanh([read,k] @ f_W.T + f_b)
        half2 FA[8] = {z, z, z, z, z, z, z, z};
        half2 FB[8] = {z, z, z, z, z, z, z, z};
#pragma unroll
        for (int j = 0; j < 32; j++) {
            const uint4 wv = fS[j * 128 + lt];
            const uint4 x0 = xh4[j];
            const uint4 x1 = xh4[32 + j];
            const int p = (j & 1) << 2;
            FA[p + 0] = __hfma2(as_h2(wv.x), as_h2(x0.x), FA[p + 0]);
            FA[p + 1] = __hfma2(as_h2(wv.y), as_h2(x0.y), FA[p + 1]);
            FA[p + 2] = __hfma2(as_h2(wv.z), as_h2(x0.z), FA[p + 2]);
            FA[p + 3] = __hfma2(as_h2(wv.w), as_h2(x0.w), FA[p + 3]);
            FB[p + 0] = __hfma2(as_h2(wv.x), as_h2(x1.x), FB[p + 0]);
            FB[p + 1] = __hfma2(as_h2(wv.y), as_h2(x1.y), FB[p + 1]);
            FB[p + 2] = __hfma2(as_h2(wv.z), as_h2(x1.z), FB[p + 2]);
            FB[p + 3] = __hfma2(as_h2(wv.w), as_h2(x1.w), FB[p + 3]);
        }
        float sA = bfv, sB = bfv;
#pragma unroll
        for (int qq = 0; qq < 8; qq++) {
            sA += h2sumf(FA[qq]);
            sB += h2sumf(FB[qq]);
        }
        const float fv0 = tanhf(sA), fv1 = tanhf(sB);
        g_f[idx0 * DD + lt] = fv0;
        g_f[idx1 * DD + lt] = fv1;
        {
            const float o0 = __shfl_xor_sync(0xffffffffu, fv0, 1);
            const float o1 = __shfl_xor_sync(0xffffffffu, fv1, 1);
            if (!(lt & 1)) {
                fh2[lt >> 1] = __floats2half2_rn(fv0, o0);
                fh2[64 + (lt >> 1)] = __floats2half2_rn(fv1, o1);
            }
        }
        __syncthreads();  // 3

        // y = yq + f @ a_Wf.T + a_b
        half2 YA[4] = {z, z, z, z}, YB[4] = {z, z, z, z};
#pragma unroll
        for (int j = 0; j < 16; j++) {
            const uint4 wv = aS[j * 128 + lt];
            const uint4 x0 = fh4[j];
            const uint4 x1 = fh4[16 + j];
            YA[0] = __hfma2(as_h2(wv.x), as_h2(x0.x), YA[0]);
            YA[1] = __hfma2(as_h2(wv.y), as_h2(x0.y), YA[1]);
            YA[2] = __hfma2(as_h2(wv.z), as_h2(x0.z), YA[2]);
            YA[3] = __hfma2(as_h2(wv.w), as_h2(x0.w), YA[3]);
            YB[0] = __hfma2(as_h2(wv.x), as_h2(x1.x), YB[0]);
            YB[1] = __hfma2(as_h2(wv.y), as_h2(x1.y), YB[1]);
            YB[2] = __hfma2(as_h2(wv.z), as_h2(x1.z), YB[2]);
            YB[3] = __hfma2(as_h2(wv.w), as_h2(x1.w), YB[3]);
        }
        float y0 = bav + yq0, y1 = bav + yq1;
#pragma unroll
        for (int qq = 0; qq < 4; qq++) {
            y0 += h2sumf(YA[qq]);
            y1 += h2sumf(YB[qq]);
        }
        {
            const float o0 = __shfl_xor_sync(0xffffffffu, y0, 1);
            const float o1 = __shfl_xor_sync(0xffffffffu, y1, 1);
            if (!(lt & 1)) {
                yh2[lt >> 1] = __floats2half2_rn(y0, o0);
                yh2[64 + (lt >> 1)] = __floats2half2_rn(y1, o1);
            }
        }
        __syncthreads();  // 4

        // e = sigmoid(y @ e_W.T + e_b), a = tanh(y @ add_W.T + add_b)
        half2 EA[4] = {z, z, z, z}, EB[4] = {z, z, z, z};
        half2 DA[4] = {z, z, z, z}, DB[4] = {z, z, z, z};
#pragma unroll
        for (int j = 0; j < 16; j++) {
            const uint4 we = eS[j * 128 + lt];
            const uint4 wa = adS[j * 128 + lt];
            const uint4 x0 = yh4[j];
            const uint4 x1 = yh4[16 + j];
            EA[0] = __hfma2(as_h2(we.x), as_h2(x0.x), EA[0]);
            EA[1] = __hfma2(as_h2(we.y), as_h2(x0.y), EA[1]);
            EA[2] = __hfma2(as_h2(we.z), as_h2(x0.z), EA[2]);
            EA[3] = __hfma2(as_h2(we.w), as_h2(x0.w), EA[3]);
            DA[0] = __hfma2(as_h2(wa.x), as_h2(x0.x), DA[0]);
            DA[1] = __hfma2(as_h2(wa.y), as_h2(x0.y), DA[1]);
            DA[2] = __hfma2(as_h2(wa.z), as_h2(x0.z), DA[2]);
            DA[3] = __hfma2(as_h2(wa.w), as_h2(x0.w), DA[3]);
            EB[0] = __hfma2(as_h2(we.x), as_h2(x1.x), EB[0]);
            EB[1] = __hfma2(as_h2(we.y), as_h2(x1.y), EB[1]);
            EB[2] = __hfma2(as_h2(we.z), as_h2(x1.z), EB[2]);
            EB[3] = __hfma2(as_h2(we.w), as_h2(x1.w), EB[3]);
            DB[0] = __hfma2(as_h2(wa.x), as_h2(x1.x), DB[0]);
            DB[1] = __hfma2(as_h2(wa.y), as_h2(x1.y), DB[1]);
            DB[2] = __hfma2(as_h2(wa.z), as_h2(x1.z), DB[2]);
            DB[3] = __hfma2(as_h2(wa.w), as_h2(x1.w), DB[3]);
        }
        float se0 = bev, se1 = bev, sd0 = badv, sd1 = badv;
#pragma unroll
        for (int qq = 0; qq < 4; qq++) {
            se0 += h2sumf(EA[qq]);
            se1 += h2sumf(EB[qq]);
            sd0 += h2sumf(DA[qq]);
            sd1 += h2sumf(DB[qq]);
        }
        const float ev0 = sigf(se0), av0 = tanhf(sd0);
        const float ev1 = sigf(se1), av1 = tanhf(sd1);
#pragma unroll
        for (int m = 0; m < MM; m++) {
            const float wm0 = wbuf[par + m];
            const float wm1 = wbuf[par + 64 + m];
            Mva[m] = fmaf(wm0, fmaf(-ev0, Mva[m], av0), Mva[m]);
            Mvb[m] = fmaf(wm1, fmaf(-ev1, Mvb[m], av1), Mvb[m]);
        }
    }
}

// ---------------- Kernel D: gi = f_all @ Wih.T + (bih + bhh) -------------------
__global__ __launch_bounds__(256) void kD(const float* __restrict__ Wih,
                                          const float* __restrict__ bih,
                                          const float* __restrict__ bhh) {
    __shared__ float sA[64][68];
    __shared__ float sB[64][68];
    const int tid = threadIdx.x;
    const int row0 = blockIdx.x * 64;
    const int n0 = blockIdx.y * 64;
    const int tx = tid & 15, ty = tid >> 4;
    float acc[4][4];
#pragma unroll
    for (int i = 0; i < 4; i++)
#pragma unroll
        for (int j = 0; j < 4; j++) acc[i][j] = 0.f;

    for (int kk = 0; kk < 128; kk += 64) {
        __syncthreads();
#pragma unroll
        for (int l = 0; l < 4; l++) {
            const int li = tid + l * 256;
            const int m = li >> 4;
            const int kq = li & 15;
            float4 v = *(const float4*)&g_f[(size_t)(row0 + m) * DD + kk + kq * 4];
            sA[kq * 4 + 0][m] = v.x; sA[kq * 4 + 1][m] = v.y;
            sA[kq * 4 + 2][m] = v.z; sA[kq * 4 + 3][m] = v.w;
            float4 u = *(const float4*)&Wih[(size_t)(n0 + m) * DD + kk + kq * 4];
            sB[kq * 4 + 0][m] = u.x; sB[kq * 4 + 1][m] = u.y;
            sB[kq * 4 + 2][m] = u.z; sB[kq * 4 + 3][m] = u.w;
        }
        __syncthreads();
#pragma unroll 8
        for (int k = 0; k < 64; k++) {
            float4 a4 = *(const float4*)&sA[k][ty * 4];
            float4 b4 = *(const float4*)&sB[k][tx * 4];
            acc[0][0] += a4.x * b4.x; acc[0][1] += a4.x * b4.y;
            acc[0][2] += a4.x * b4.z; acc[0][3] += a4.x * b4.w;
            acc[1][0] += a4.y * b4.x; acc[1][1] += a4.y * b4.y;
            acc[1][2] += a4.y * b4.z; acc[1][3] += a4.y * b4.w;
            acc[2][0] += a4.z * b4.x; acc[2][1] += a4.z * b4.y;
            acc[2][2] += a4.z * b4.z; acc[2][3] += a4.z * b4.w;
            acc[3][0] += a4.w * b4.x; acc[3][1] += a4.w * b4.y;
            acc[3][2] += a4.w * b4.z; acc[3][3] += a4.w * b4.w;
        }
    }
#pragma unroll
    for (int i = 0; i < 4; i++) {
        const int rrow = row0 + ty * 4 + i;
#pragma unroll
        for (int j = 0; j < 4; j++) {
            const int n = n0 + tx * 4 + j;
            g_gi[(size_t)rrow * G4 + n] = acc[i][j] + bih[n] + bhh[n];
        }
    }
}

// ---------------- Kernel E: LSTM scan, 256 thr = 2 groups x 2 batches ----------
#define E_SMEM (131072 + 1024 + 64)
__global__ __launch_bounds__(256) void kE(const float* __restrict__ Whh,
                                          const float* __restrict__ pW,
                                          const float* __restrict__ pb,
                                          float* __restrict__ out) {
    extern __shared__ char sm2[];
    uint4* wS = (uint4*)sm2;  // [16*512]
    const int tid = threadIdx.x;
    const int grp = tid >> 7, lt = tid & 127;
    uint4* hh4 = (uint4*)(sm2 + 131072) + grp * 32;  // [2 batch][16]
    half2* hh2 = (half2*)hh4;
    float* red = (float*)(sm2 + 132096) + grp * 8;
    const int b0 = blockIdx.x * 4 + grp * 2;

    for (int i = tid; i < 64 * G4; i += 256) {
        const int jp = i >> 9, g = i & 511;
        ((half2*)wS)[(((jp >> 2) * G4 + g) << 2) + (jp & 3)] =
            __floats2half2_rn(Whh[g * DD + 2 * jp], Whh[g * DD + 2 * jp + 1]);
    }
    const float pw = pW[lt];
    const float pbv = pb[0];
    float h0 = 0.f, c0 = 0.f, h1 = 0.f, c1 = 0.f;
    __syncthreads();

    const half2 z = __float2half2_rn(0.f);
    for (int t = 0; t < TT; t++) {
        const int idx0 = b0 * TT + t, idx1 = idx0 + TT;
        float cin0, cin1;
        {
            float hv;
            if (g_match[idx0]) {
                const int pv = g_prev[idx0];
                hv = g_H[(size_t)(b0 * TT + pv) * DD + lt];
                cin0 = g_C[(size_t)(b0 * TT + pv) * DD + lt];
            } else { hv = h0; cin0 = c0; }
            const float o_ = __shfl_xor_sync(0xffffffffu, hv, 1);
            if (!(lt & 1)) hh2[lt >> 1] = __floats2half2_rn(hv, o_);
        }
        {
            float hv;
            if (g_match[idx1]) {
                const int pv = g_prev[idx1];
                hv = g_H[(size_t)((b0 + 1) * TT + pv) * DD + lt];
                cin1 = g_C[(size_t)((b0 + 1) * TT + pv) * DD + lt];
            } else { hv = h1; cin1 = c1; }
            const float o_ = __shfl_xor_sync(0xffffffffu, hv, 1);
            if (!(lt & 1)) hh2[64 + (lt >> 1)] = __floats2half2_rn(hv, o_);
        }
        __syncthreads();  // A

        half2 acc[16];
#pragma unroll
        for (int qq = 0; qq < 16; qq++) acc[qq] = z;
#pragma unroll
        for (int j = 0; j < 16; j++) {
            const uint4 x0 = hh4[j];
            const uint4 x1 = hh4[16 + j];
            const uint4 wi = wS[j * G4 + lt];
            const uint4 wf = wS[j * G4 + 128 + lt];
            const uint4 wg = wS[j * G4 + 256 + lt];
            const uint4 wo = wS[j * G4 + 384 + lt];
            const int p = j & 1;
            acc[0 + p] = __hfma2(as_h2(wi.x), as_h2(x0.x), acc[0 + p]);
            acc[0 + p] = __hfma2(as_h2(wi.y), as_h2(x0.y), acc[0 + p]);
            acc[0 + p] = __hfma2(as_h2(wi.z), as_h2(x0.z), acc[0 + p]);
            acc[0 + p] = __hfma2(as_h2(wi.w), as_h2(x0.w), acc[0 + p]);
            acc[2 + p] = __hfma2(as_h2(wi.x), as_h2(x1.x), acc[2 + p]);
            acc[2 + p] = __hfma2(as_h2(wi.y), as_h2(x1.y), acc[2 + p]);
            acc[2 + p] = __hfma2(as_h2(wi.z), as_h2(x1.z), acc[2 + p]);
            acc[2 + p] = __hfma2(as_h2(wi.w), as_h2(x1.w), acc[2 + p]);
            acc[4 + p] = __hfma2(as_h2(wf.x), as_h2(x0.x), acc[4 + p]);
            acc[4 + p] = __hfma2(as_h2(wf.y), as_h2(x0.y), acc[4 + p]);
            acc[4 + p] = __hfma2(as_h2(wf.z), as_h2(x0.z), acc[4 + p]);
            acc[4 + p] = __hfma2(as_h2(wf.w), as_h2(x0.w), acc[4 + p]);
            acc[6 + p] = __hfma2(as_h2(wf.x), as_h2(x1.x), acc[6 + p]);
            acc[6 + p] = __hfma2(as_h2(wf.y), as_h2(x1.y), acc[6 + p]);
            acc[6 + p] = __hfma2(as_h2(wf.z), as_h2(x1.z), acc[6 + p]);
            acc[6 + p] = __hfma2(as_h2(wf.w), as_h2(x1.w), acc[6 + p]);
            acc[8 + p] = __hfma2(as_h2(wg.x), as_h2(x0.x), acc[8 + p]);
            acc[8 + p] = __hfma2(as_h2(wg.y), as_h2(x0.y), acc[8 + p]);
            acc[8 + p] = __hfma2(as_h2(wg.z), as_h2(x0.z), acc[8 + p]);
            acc[8 + p] = __hfma2(as_h2(wg.w), as_h2(x0.w), acc[8 + p]);
            acc[10 + p] = __hfma2(as_h2(wg.x), as_h2(x1.x), acc[10 + p]);
            acc[10 + p] = __hfma2(as_h2(wg.y), as_h2(x1.y), acc[10 + p]);
            acc[10 + p] = __hfma2(as_h2(wg.z), as_h2(x1.z), acc[10 + p]);
            acc[10 + p] = __hfma2(as_h2(wg.w), as_h2(x1.w), acc[10 + p]);
            acc[12 + p] = __hfma2(as_h2(wo.x), as_h2(x0.x), acc[12 + p]);
            acc[12 + p] = __hfma2(as_h2(wo.y), as_h2(x0.y), acc[12 + p]);
            acc[12 + p] = __hfma2(as_h2(wo.z), as_h2(x0.z), acc[12 + p]);
            acc[12 + p] = __hfma2(as_h2(wo.w), as_h2(x0.w), acc[12 + p]);
            acc[14 + p] = __hfma2(as_h2(wo.x), as_h2(x1.x), acc[14 + p]);
            acc[14 + p] = __hfma2(as_h2(wo.y), as_h2(x1.y), acc[14 + p]);
            acc[14 + p] = __hfma2(as_h2(wo.z), as_h2(x1.z), acc[14 + p]);
            acc[14 + p] = __hfma2(as_h2(wo.w), as_h2(x1.w), acc[14 + p]);
        }
        float s[8];
#pragma unroll
        for (int qq = 0; qq < 8; qq++)
            s[qq] = h2sumf(acc[2 * qq]) + h2sumf(acc[2 * qq + 1]);
        const float gi0 = g_gi[(size_t)idx0 * G4 + lt] + s[0];
        const float gf0 = g_gi[(size_t)idx0 * G4 + 128 + lt] + s[2];
        const float gg0 = g_gi[(size_t)idx0 * G4 + 256 + lt] + s[4];
        const float go0 = g_gi[(size_t)idx0 * G4 + 384 + lt] + s[6];
        const float gi1 = g_gi[(size_t)idx1 * G4 + lt] + s[1];
        const float gf1 = g_gi[(size_t)idx1 * G4 + 128 + lt] + s[3];
        const float gg1 = g_gi[(size_t)idx1 * G4 + 256 + lt] + s[5];
        const float go1 = g_gi[(size_t)idx1 * G4 + 384 + lt] + s[7];
        c0 = sigf(gf0) * cin0 + sigf(gi0) * tanhf(gg0);
        h0 = sigf(go0) * tanhf(c0);
        c1 = sigf(gf1) * cin1 + sigf(gi1) * tanhf(gg1);
        h1 = sigf(go1) * tanhf(c1);
        g_H[(size_t)idx0 * DD + lt] = h0;
        g_C[(size_t)idx0 * DD + lt] = c0;
        g_H[(size_t)idx1 * DD + lt] = h1;
        g_C[(size_t)idx1 * DD + lt] = c1;
        const float p0 = warp_sum(h0 * pw);
        const float p1 = warp_sum(h1 * pw);
        if (!(lt & 31)) {
            red[lt >> 5] = p0;
            red[4 + (lt >> 5)] = p1;
        }
        __syncthreads();  // B
        if (lt == 0) {
            out[idx0] = sigf(red[0] + red[1] + red[2] + red[3] + pbv);
            out[idx1] = sigf(red[4] + red[5] + red[6] + red[7] + pbv);
        }
    }
}

// ---------------- launch ----------------
extern "C" void kernel_launch(void* const* d_in, const int* in_sizes, int n_in,
                              void* d_out, int out_size) {
    const int* q = (const int*)d_in[0];
    const int* r = (const int*)d_in[1];
    const float* k_emb = (const float*)d_in[2];
    const float* Mk = (const float*)d_in[3];
    const float* Mv0 = (const float*)d_in[4];
    const float* fW = (const float*)d_in[5];
    const float* fb = (const float*)d_in[6];
    const float* aW = (const float*)d_in[7];
    const float* ab = (const float*)d_in[8];
    const float* eW = (const float*)d_in[9];
    const float* eb = (const float*)d_in[10];
    const float* addW = (const float*)d_in[11];
    const float* addb = (const float*)d_in[12];
    const float* Wih = (const float*)d_in[13];
    const float* Whh = (const float*)d_in[14];
    const float* bih = (const float*)d_in[15];
    const float* bhh = (const float*)d_in[16];
    const float* pW = (const float*)d_in[17];
    const float* pb = (const float*)d_in[18];
    float* out = (float*)d_out;

    cudaFuncSetAttribute(kC, cudaFuncAttributeMaxDynamicSharedMemorySize, C_SMEM);
    cudaFuncSetAttribute(kE, cudaFuncAttributeMaxDynamicSharedMemorySize, E_SMEM);

    kA<<<256, 256>>>(q, r, k_emb, Mk, aW);
    kB<<<RR / 8, 256>>>();
    kC<<<BSZ / 4, 256, C_SMEM>>>(fW, fb, aW, ab, eW, eb, addW, addb, Mv0);
    kD<<<dim3(RR / 64, G4 / 64), 256>>>(Wih, bih, bhh);
    kE<<<BSZ / 4, 256, E_SMEM>>>(Whh, pW, pb, out);
}

// round 7
// speedup vs baseline: 1.7981x; 1.5941x over previous
#include <cuda_runtime.h>
#include <cuda_fp16.h>

#define BSZ 32
#define TT 512
#define DD 128
#define MM 50
#define NUMC 4096
#define AWC (NUMC + DD)
#define G4 512
#define RR (BSZ * TT)

// ---------------- scratch (static device arrays; no allocation) ----------------
__device__ float g_k[RR * DD];
__device__ float g_yq[RR * DD];
__device__ float g_w[RR * MM];
__device__ unsigned long long g_pack[RR * 2];
__device__ int g_prev[RR];
__device__ int g_match[RR];
__device__ float g_f[RR * DD];
__device__ float g_gi[RR * G4];
__device__ float g_H[RR * DD];
__device__ float g_C[RR * DD];

__device__ __forceinline__ float warp_sum(float v) {
#pragma unroll
    for (int o = 16; o; o >>= 1) v += __shfl_xor_sync(0xffffffffu, v, o);
    return v;
}

__device__ __forceinline__ half2 as_h2(unsigned u) { return *reinterpret_cast<half2*>(&u); }
__device__ __forceinline__ float sigf(float x) { return 1.f / (1.f + __expf(-x)); }
__device__ __forceinline__ float h2sumf(half2 v) {
    const float2 e = __half22float2(v);
    return e.x + e.y;
}

// ---------------- Kernel A: gather + logits + softmax + quantize/pack ----------
__global__ __launch_bounds__(256) void kA(const int* __restrict__ q,
                                          const int* __restrict__ r,
                                          const float* __restrict__ k_emb,
                                          const float* __restrict__ Mk,
                                          const float* __restrict__ aW) {
    __shared__ float sMk[MM * DD];
    __shared__ float sk[DD];
    __shared__ float slog[MM];
    const int tid = threadIdx.x;
    for (int i = tid; i < MM * DD; i += 256) sMk[i] = Mk[i];
    const int base = blockIdx.x * 64;
    const int warp = tid >> 5, lane = tid & 31;

    for (int p = 0; p < 64; p++) {
        const int idx = base + p;
        __syncthreads();
        if (tid < DD) {
            const int qv = q[idx];
            const float kv = k_emb[qv * DD + tid];
            sk[tid] = kv;
            g_k[idx * DD + tid] = kv;
            g_yq[idx * DD + tid] = aW[tid * AWC + qv] * (float)r[idx];
        }
        __syncthreads();
        for (int m = warp; m < MM; m += 8) {
            float s = 0.f;
#pragma unroll
            for (int c = 0; c < 4; c++) s = fmaf(sk[c * 32 + lane], sMk[m * DD + c * 32 + lane], s);
            s = warp_sum(s);
            if (lane == 0) slog[m] = s;
        }
        __syncthreads();
        if (warp == 0) {
            float l0 = (lane < MM) ? slog[lane] : -1e30f;
            float l1 = (lane + 32 < MM) ? slog[lane + 32] : -1e30f;
            float mx = fmaxf(l0, l1);
#pragma unroll
            for (int o = 16; o; o >>= 1) mx = fmaxf(mx, __shfl_xor_sync(0xffffffffu, mx, o));
            float e0 = (lane < MM) ? expf(l0 - mx) : 0.f;
            float e1 = (lane + 32 < MM) ? expf(l1 - mx) : 0.f;
            float ssum = warp_sum(e0 + e1);
            float w0 = e0 / ssum, w1 = e1 / ssum;
            if (lane < MM) g_w[idx * MM + lane] = w0;
            if (lane + 32 < MM) g_w[idx * MM + lane + 32] = w1;
            const float ta = 0.075f;
            const float dba = (float)(0.088 - 0.075);
            const float dcb = (float)(1.0 - 0.088);
            float tw0 = fmaxf(fminf((w0 - ta) / dba, (1.0f - w0) / dcb), 0.f);
            float tw1 = fmaxf(fminf((w1 - ta) / dba, (1.0f - w1) / dcb), 0.f);
            int c0 = (lane < MM) ? (tw0 >= 0.6f ? 2 : (tw0 >= 0.1f ? 1 : 0)) : 0;
            int c1 = (lane + 32 < MM) ? (tw1 >= 0.6f ? 2 : (tw1 >= 0.1f ? 1 : 0)) : 0;
            unsigned b00 = __ballot_sync(0xffffffffu, c0 & 1);
            unsigned b01 = __ballot_sync(0xffffffffu, c0 >> 1);
            unsigned b10 = __ballot_sync(0xffffffffu, c1 & 1);
            unsigned b11 = __ballot_sync(0xffffffffu, c1 >> 1);
            if (lane == 0) {
                g_pack[idx * 2 + 0] = (unsigned long long)b00 | ((unsigned long long)b01 << 32);
                g_pack[idx * 2 + 1] = (unsigned long long)b10 | ((unsigned long long)b11 << 32);
            }
        }
    }
}

// ---------------- Kernel B: matched/prev via warp ballot backward scan ---------
__global__ __launch_bounds__(256) void kB() {
    const int gw = blockIdx.x * 8 + (threadIdx.x >> 5);
    const int lane = threadIdx.x & 31;
    const int b = gw / TT, i = gw % TT;
    const unsigned long long m0 = g_pack[gw * 2], m1 = g_pack[gw * 2 + 1];
    const unsigned long long* rp = &g_pack[(size_t)b * TT * 2];
    int prev = 0, matched = 0;
    for (int base = i - 1; base >= 0; base -= 32) {
        const int j = base - lane;
        const bool eq = (j >= 0) && (rp[j * 2] == m0) && (rp[j * 2 + 1] == m1);
        const unsigned msk = __ballot_sync(0xffffffffu, eq);
        if (msk) { matched = 1; prev = base - (__ffs(msk) - 1); break; }
    }
    if (lane == 0) { g_prev[gw] = prev; g_match[gw] = matched; }
}

// ---------------- Kernel C: memory-network scan -------------------------------
// 256 threads: o = tid>>1 (output elem), p = tid&1 (batch of the pair).
// smem: fS 0..65536 | aS ..98304 | eS ..131072 | adS ..163840
//       xh4[65] @163840+0 | fh4[33] @+1088 | yh4[33] @+1664 | wbuf[288f] @+2240
#define C_SMEM (163840 + 2240 + 1152)
__global__ __launch_bounds__(256) void kC(const float* __restrict__ fW,
                                          const float* __restrict__ fb,
                                          const float* __restrict__ aW,
                                          const float* __restrict__ ab,
                                          const float* __restrict__ eW,
                                          const float* __restrict__ eb,
                                          const float* __restrict__ addW,
                                          const float* __restrict__ addb,
                                          const float* __restrict__ Mv0) {
    extern __shared__ char sm[];
    uint4* fS = (uint4*)sm;                        // [32][128]
    uint4* aS = (uint4*)(sm + 65536);              // [16][128]
    uint4* eS = (uint4*)(sm + 98304);              // [16][128]
    uint4* adS = (uint4*)(sm + 131072);            // [16][128]
    uint4* xh4 = (uint4*)(sm + 163840);            // [65]: A@0, B@33
    uint4* fh4 = (uint4*)(sm + 163840 + 1088);     // [33]: A@0, B@17
    uint4* yh4 = (uint4*)(sm + 163840 + 1664);     // [33]: A@0, B@17
    float* wbuf = (float*)(sm + 163840 + 2240);    // [2 par][2 p][72]
    half2* xh2 = (half2*)xh4;
    half2* fh2 = (half2*)fh4;
    half2* yh2 = (half2*)yh4;

    const int tid = threadIdx.x;
    const int o = tid >> 1, p = tid & 1;
    const int b0 = blockIdx.x * 2;
    const half2 z = __float2half2_rn(0.f);

    for (int i = tid; i < 128 * 128; i += 256) {
        const int jp = i >> 7, oo = i & 127;
        ((half2*)fS)[(((jp >> 2) * 128 + oo) << 2) + (jp & 3)] =
            __floats2half2_rn(fW[oo * 256 + 2 * jp], fW[oo * 256 + 2 * jp + 1]);
    }
    for (int i = tid; i < 64 * 128; i += 256) {
        const int jp = i >> 7, oo = i & 127;
        const int d = (((jp >> 2) * 128 + oo) << 2) + (jp & 3);
        ((half2*)aS)[d] =
            __floats2half2_rn(aW[oo * AWC + NUMC + 2 * jp], aW[oo * AWC + NUMC + 2 * jp + 1]);
        ((half2*)eS)[d] = __floats2half2_rn(eW[oo * 128 + 2 * jp], eW[oo * 128 + 2 * jp + 1]);
        ((half2*)adS)[d] = __floats2half2_rn(addW[oo * 128 + 2 * jp], addW[oo * 128 + 2 * jp + 1]);
    }
    const float bfv = fb[o], bav = ab[o], bev = eb[o], badv = addb[o];
    float Mv[MM];
#pragma unroll
    for (int m = 0; m < MM; m++) Mv[m] = Mv0[m * DD + o];
    __syncthreads();

    const int xbase = p * 132;   // half2 base in xh4 (33 uint4 * 4)
    const int fbase = p * 68;    // half2 base in fh4 (17 uint4 * 4)
    const int x4 = p * 33, f4 = p * 17;
    const int wb = p * 72;

    for (int t = 0; t < TT; t++) {
        const int idx0 = b0 * TT + t, idx1 = idx0 + TT;
        const int idxp = p ? idx1 : idx0;
        const int par = (t & 1) * 144;
        // stage w (both batches) and k (own batch)
        if (tid < MM) wbuf[par + tid] = g_w[idx0 * MM + tid];
        else if (tid >= 128 && tid < 128 + MM) wbuf[par + 72 + tid - 128] = g_w[idx1 * MM + tid - 128];
        {
            const float kv = g_k[idxp * DD + o];
            const float kn = __shfl_xor_sync(0xffffffffu, kv, 2);
            if (!(tid & 2)) xh2[xbase + 64 + (o >> 1)] = __floats2half2_rn(kv, kn);
        }
        const float yqv = g_yq[idxp * DD + o];
        __syncthreads();  // B1

        // phase 1: read = w @ Mv (own batch, full dot in registers)
        float r0 = 0.f, r1 = 0.f;
#pragma unroll
        for (int m = 0; m < MM; m += 2) {
            r0 = fmaf(wbuf[par + wb + m], Mv[m], r0);
            r1 = fmaf(wbuf[par + wb + m + 1], Mv[m + 1], r1);
        }
        {
            const float rv = r0 + r1;
            const float rn = __shfl_xor_sync(0xffffffffu, rv, 2);
            if (!(tid & 2)) xh2[xbase + (o >> 1)] = __floats2half2_rn(rv, rn);
        }
        __syncthreads();  // B2

        // phase 2: f = tanh([read,k] @ fW.T + fb)
        half2 F[8] = {z, z, z, z, z, z, z, z};
#pragma unroll
        for (int j = 0; j < 32; j++) {
            const uint4 wv = fS[j * 128 + o];
            const uint4 xv = xh4[x4 + j];
            const int q4 = (j & 1) << 2;
            F[q4 + 0] = __hfma2(as_h2(wv.x), as_h2(xv.x), F[q4 + 0]);
            F[q4 + 1] = __hfma2(as_h2(wv.y), as_h2(xv.y), F[q4 + 1]);
            F[q4 + 2] = __hfma2(as_h2(wv.z), as_h2(xv.z), F[q4 + 2]);
            F[q4 + 3] = __hfma2(as_h2(wv.w), as_h2(xv.w), F[q4 + 3]);
        }
        float sf = bfv;
#pragma unroll
        for (int qq = 0; qq < 8; qq++) sf += h2sumf(F[qq]);
        const float fv = tanhf(sf);
        g_f[idxp * DD + o] = fv;
        {
            const float fn = __shfl_xor_sync(0xffffffffu, fv, 2);
            if (!(tid & 2)) fh2[fbase + (o >> 1)] = __floats2half2_rn(fv, fn);
        }
        __syncthreads();  // B3

        // phase 3: y = yq + f @ aWf.T + ab
        half2 Y[4] = {z, z, z, z};
#pragma unroll
        for (int j = 0; j < 16; j++) {
            const uint4 wv = aS[j * 128 + o];
            const uint4 xv = fh4[f4 + j];
            Y[0] = __hfma2(as_h2(wv.x), as_h2(xv.x), Y[0]);
            Y[1] = __hfma2(as_h2(wv.y), as_h2(xv.y), Y[1]);
            Y[2] = __hfma2(as_h2(wv.z), as_h2(xv.z), Y[2]);
            Y[3] = __hfma2(as_h2(wv.w), as_h2(xv.w), Y[3]);
        }
        float yv = bav + yqv;
#pragma unroll
        for (int qq = 0; qq < 4; qq++) yv += h2sumf(Y[qq]);
        {
            const float yn = __shfl_xor_sync(0xffffffffu, yv, 2);
            if (!(tid & 2)) yh2[fbase + (o >> 1)] = __floats2half2_rn(yv, yn);
        }
        __syncthreads();  // B4

        // phase 4: e = sigmoid(y@eW.T+eb), a = tanh(y@addW.T+addb)
        half2 E[4] = {z, z, z, z}, Dg[4] = {z, z, z, z};
#pragma unroll
        for (int j = 0; j < 16; j++) {
            const uint4 we = eS[j * 128 + o];
            const uint4 wa = adS[j * 128 + o];
            const uint4 xv = yh4[f4 + j];
            E[0] = __hfma2(as_h2(we.x), as_h2(xv.x), E[0]);
            E[1] = __hfma2(as_h2(we.y), as_h2(xv.y), E[1]);
            E[2] = __hfma2(as_h2(we.z), as_h2(xv.z), E[2]);
            E[3] = __hfma2(as_h2(we.w), as_h2(xv.w), E[3]);
            Dg[0] = __hfma2(as_h2(wa.x), as_h2(xv.x), Dg[0]);
            Dg[1] = __hfma2(as_h2(wa.y), as_h2(xv.y), Dg[1]);
            Dg[2] = __hfma2(as_h2(wa.z), as_h2(xv.z), Dg[2]);
            Dg[3] = __hfma2(as_h2(wa.w), as_h2(xv.w), Dg[3]);
        }
        float se = bev, sd = badv;
#pragma unroll
        for (int qq = 0; qq < 4; qq++) {
            se += h2sumf(E[qq]);
            sd += h2sumf(Dg[qq]);
        }
        const float ev = sigf(se), av = tanhf(sd);
        // phase 5: Mv update
#pragma unroll
        for (int m = 0; m < MM; m++) {
            const float wm = wbuf[par + wb + m];
            Mv[m] = fmaf(wm, fmaf(-ev, Mv[m], av), Mv[m]);
        }
    }
}

// ---------------- Kernel D: gi = f_all @ Wih.T + (bih + bhh) -------------------
__global__ __launch_bounds__(256) void kD(const float* __restrict__ Wih,
                                          const float* __restrict__ bih,
                                          const float* __restrict__ bhh) {
    __shared__ float sA[64][68];
    __shared__ float sB[64][68];
    const int tid = threadIdx.x;
    const int row0 = blockIdx.x * 64;
    const int n0 = blockIdx.y * 64;
    const int tx = tid & 15, ty = tid >> 4;
    float acc[4][4];
#pragma unroll
    for (int i = 0; i < 4; i++)
#pragma unroll
        for (int j = 0; j < 4; j++) acc[i][j] = 0.f;

    for (int kk = 0; kk < 128; kk += 64) {
        __syncthreads();
#pragma unroll
        for (int l = 0; l < 4; l++) {
            const int li = tid + l * 256;
            const int m = li >> 4;
            const int kq = li & 15;
            float4 v = *(const float4*)&g_f[(size_t)(row0 + m) * DD + kk + kq * 4];
            sA[kq * 4 + 0][m] = v.x; sA[kq * 4 + 1][m] = v.y;
            sA[kq * 4 + 2][m] = v.z; sA[kq * 4 + 3][m] = v.w;
            float4 u = *(const float4*)&Wih[(size_t)(n0 + m) * DD + kk + kq * 4];
            sB[kq * 4 + 0][m] = u.x; sB[kq * 4 + 1][m] = u.y;
            sB[kq * 4 + 2][m] = u.z; sB[kq * 4 + 3][m] = u.w;
        }
        __syncthreads();
#pragma unroll 8
        for (int k = 0; k < 64; k++) {
            float4 a4 = *(const float4*)&sA[k][ty * 4];
            float4 b4 = *(const float4*)&sB[k][tx * 4];
            acc[0][0] += a4.x * b4.x; acc[0][1] += a4.x * b4.y;
            acc[0][2] += a4.x * b4.z; acc[0][3] += a4.x * b4.w;
            acc[1][0] += a4.y * b4.x; acc[1][1] += a4.y * b4.y;
            acc[1][2] += a4.y * b4.z; acc[1][3] += a4.y * b4.w;
            acc[2][0] += a4.z * b4.x; acc[2][1] += a4.z * b4.y;
            acc[2][2] += a4.z * b4.z; acc[2][3] += a4.z * b4.w;
            acc[3][0] += a4.w * b4.x; acc[3][1] += a4.w * b4.y;
            acc[3][2] += a4.w * b4.z; acc[3][3] += a4.w * b4.w;
        }
    }
#pragma unroll
    for (int i = 0; i < 4; i++) {
        const int rrow = row0 + ty * 4 + i;
#pragma unroll
        for (int j = 0; j < 4; j++) {
            const int n = n0 + tx * 4 + j;
            g_gi[(size_t)rrow * G4 + n] = acc[i][j] + bih[n] + bhh[n];
        }
    }
}

// ---------------- Kernel E: LSTM scan ------------------------------------------
// 256 threads: d = tid>>1 (output dim), p = tid&1 (batch of the pair).
#define E_SMEM (131072 + 576 + 64)
__global__ __launch_bounds__(256) void kE(const float* __restrict__ Whh,
                                          const float* __restrict__ pW,
                                          const float* __restrict__ pb,
                                          float* __restrict__ out) {
    extern __shared__ char sm2[];
    uint4* wS = (uint4*)sm2;                     // [16][512]
    uint4* hh4 = (uint4*)(sm2 + 131072);         // [33]: A@0, B@17
    half2* hh2 = (half2*)hh4;
    float* red = (float*)(sm2 + 131072 + 576);   // [16]
    const int tid = threadIdx.x;
    const int d = tid >> 1, p = tid & 1;
    const int b0 = blockIdx.x * 2;
    const half2 z = __float2half2_rn(0.f);

    for (int i = tid; i < 64 * G4; i += 256) {
        const int jp = i >> 9, g = i & 511;
        ((half2*)wS)[(((jp >> 2) * G4 + g) << 2) + (jp & 3)] =
            __floats2half2_rn(Whh[g * DD + 2 * jp], Whh[g * DD + 2 * jp + 1]);
    }
    const float pw = pW[d];
    const float pbv = pb[0];
    float h = 0.f, c = 0.f;
    __syncthreads();

    const int hbase = p * 68;  // half2 base
    const int h4 = p * 17;

    for (int t = 0; t < TT; t++) {
        const int idx0 = b0 * TT + t, idx1 = idx0 + TT;
        const int idxp = p ? idx1 : idx0;
        const int bB = b0 + p;
        float cin;
        {
            float hv;
            if (g_match[idxp]) {
                const int pv = g_prev[idxp];
                hv = g_H[(size_t)(bB * TT + pv) * DD + d];
                cin = g_C[(size_t)(bB * TT + pv) * DD + d];
            } else {
                hv = h; cin = c;
            }
            const float hn = __shfl_xor_sync(0xffffffffu, hv, 2);
            if (!(tid & 2)) hh2[hbase + (d >> 1)] = __floats2half2_rn(hv, hn);
        }
        float gI = g_gi[(size_t)idxp * G4 + d];
        float gF = g_gi[(size_t)idxp * G4 + 128 + d];
        float gG = g_gi[(size_t)idxp * G4 + 256 + d];
        float gO = g_gi[(size_t)idxp * G4 + 384 + d];
        __syncthreads();  // A

        half2 ai[2] = {z, z}, af[2] = {z, z}, ag[2] = {z, z}, ao[2] = {z, z};
#pragma unroll
        for (int j = 0; j < 16; j++) {
            const uint4 xv = hh4[h4 + j];
            const uint4 wi = wS[j * G4 + d];
            const uint4 wf = wS[j * G4 + 128 + d];
            const uint4 wg = wS[j * G4 + 256 + d];
            const uint4 wo = wS[j * G4 + 384 + d];
            const int q = j & 1;
            ai[q] = __hfma2(as_h2(wi.x), as_h2(xv.x), ai[q]);
            ai[q] = __hfma2(as_h2(wi.y), as_h2(xv.y), ai[q]);
            ai[q] = __hfma2(as_h2(wi.z), as_h2(xv.z), ai[q]);
            ai[q] = __hfma2(as_h2(wi.w), as_h2(xv.w), ai[q]);
            af[q] = __hfma2(as_h2(wf.x), as_h2(xv.x), af[q]);
            af[q] = __hfma2(as_h2(wf.y), as_h2(xv.y), af[q]);
            af[q] = __hfma2(as_h2(wf.z), as_h2(xv.z), af[q]);
            af[q] = __hfma2(as_h2(wf.w), as_h2(xv.w), af[q]);
            ag[q] = __hfma2(as_h2(wg.x), as_h2(xv.x), ag[q]);
            ag[q] = __hfma2(as_h2(wg.y), as_h2(xv.y), ag[q]);
            ag[q] = __hfma2(as_h2(wg.z), as_h2(xv.z), ag[q]);
            ag[q] = __hfma2(as_h2(wg.w), as_h2(xv.w), ag[q]);
            ao[q] = __hfma2(as_h2(wo.x), as_h2(xv.x), ao[q]);
            ao[q] = __hfma2(as_h2(wo.y), as_h2(xv.y), ao[q]);
            ao[q] = __hfma2(as_h2(wo.z), as_h2(xv.z), ao[q]);
            ao[q] = __hfma2(as_h2(wo.w), as_h2(xv.w), ao[q]);
        }
        gI += h2sumf(ai[0]) + h2sumf(ai[1]);
        gF += h2sumf(af[0]) + h2sumf(af[1]);
        gG += h2sumf(ag[0]) + h2sumf(ag[1]);
        gO += h2sumf(ao[0]) + h2sumf(ao[1]);
        c = sigf(gF) * cin + sigf(gI) * tanhf(gG);
        h = sigf(gO) * tanhf(c);
        g_H[(size_t)idxp * DD + d] = h;
        g_C[(size_t)idxp * DD + d] = c;
        // parity-preserving butterfly: sums over same-p lanes
        float v = h * pw;
        v += __shfl_xor_sync(0xffffffffu, v, 2);
        v += __shfl_xor_sync(0xffffffffu, v, 4);
        v += __shfl_xor_sync(0xffffffffu, v, 8);
        v += __shfl_xor_sync(0xffffffffu, v, 16);
        if ((tid & 31) < 2) red[p * 8 + (tid >> 5)] = v;
        __syncthreads();  // B
        if (tid == 0) {
            float s0 = 0.f, s1 = 0.f;
#pragma unroll
            for (int wq = 0; wq < 8; wq++) { s0 += red[wq]; s1 += red[8 + wq]; }
            out[idx0] = sigf(s0 + pbv);
            out[idx1] = sigf(s1 + pbv);
        }
    }
}

// ---------------- launch ----------------
extern "C" void kernel_launch(void* const* d_in, const int* in_sizes, int n_in,
                              void* d_out, int out_size) {
    const int* q = (const int*)d_in[0];
    const int* r = (const int*)d_in[1];
    const float* k_emb = (const float*)d_in[2];
    const float* Mk = (const float*)d_in[3];
    const float* Mv0 = (const float*)d_in[4];
    const float* fW = (const float*)d_in[5];
    const float* fb = (const float*)d_in[6];
    const float* aW = (const float*)d_in[7];
    const float* ab = (const float*)d_in[8];
    const float* eW = (const float*)d_in[9];
    const float* eb = (const float*)d_in[10];
    const float* addW = (const float*)d_in[11];
    const float* addb = (const float*)d_in[12];
    const float* Wih = (const float*)d_in[13];
    const float* Whh = (const float*)d_in[14];
    const float* bih = (const float*)d_in[15];
    const float* bhh = (const float*)d_in[16];
    const float* pW = (const float*)d_in[17];
    const float* pb = (const float*)d_in[18];
    float* out = (float*)d_out;

    cudaFuncSetAttribute(kC, cudaFuncAttributeMaxDynamicSharedMemorySize, C_SMEM);
    cudaFuncSetAttribute(kE, cudaFuncAttributeMaxDynamicSharedMemorySize, E_SMEM);

    kA<<<256, 256>>>(q, r, k_emb, Mk, aW);
    kB<<<RR / 8, 256>>>();
    kC<<<BSZ / 2, 256, C_SMEM>>>(fW, fb, aW, ab, eW, eb, addW, addb, Mv0);
    kD<<<dim3(RR / 64, G4 / 64), 256>>>(Wih, bih, bhh);
    kE<<<BSZ / 2, 256, E_SMEM>>>(Whh, pW, pb, out);
}